// round 1
// baseline (speedup 1.0000x reference)
#include <cuda_runtime.h>
#include <math.h>

#define BATCH 4
#define DIM   128
#define NPTS  4096
#define NB    (BATCH*NPTS)          // 16384 rows total
#define INV_T 14.285714285714286f   // 1/0.07
#define MCHUNKS 32
#define MPERCHUNK (NPTS/MCHUNKS)    // 128

// ---- device scratch (no allocations allowed) ----
__device__ float g_invq[NB];
__device__ float g_invk[NB];
__device__ float g_sumk[BATCH*DIM];
__device__ float g_m2part[(size_t)BATCH*MCHUNKS*DIM*DIM]; // 8 MB
__device__ float g_m2[BATCH*DIM*DIM];
__device__ float g_rowpart[512];

// ---------------------------------------------------------------------------
// K0: L1 norms per (b,n) for q and k. layout: x[b][d][n], n contiguous.
// ---------------------------------------------------------------------------
__global__ __launch_bounds__(256) void k_norms(const float* __restrict__ q,
                                               const float* __restrict__ k) {
    int t = blockIdx.x * blockDim.x + threadIdx.x;   // 0..16383
    int b = t >> 12;
    int n = t & (NPTS - 1);
    const float* qp = q + (size_t)b * DIM * NPTS + n;
    const float* kp = k + (size_t)b * DIM * NPTS + n;
    float sq = 0.f, sk = 0.f;
#pragma unroll 8
    for (int d = 0; d < DIM; d++) {
        sq += fabsf(qp[(size_t)d * NPTS]);
        sk += fabsf(kp[(size_t)d * NPTS]);
    }
    g_invq[t] = 1.0f / fmaxf(sq, 1e-12f);
    g_invk[t] = 1.0f / fmaxf(sk, 1e-12f);
}

// ---------------------------------------------------------------------------
// K1: sumk[b][d] = sum_n k[b][d][n] * invk[b][n]. One block per (b,d).
// ---------------------------------------------------------------------------
__global__ __launch_bounds__(256) void k_sumk(const float* __restrict__ k) {
    int bd = blockIdx.x;                 // 0..511
    int b  = bd >> 7;
    int d  = bd & (DIM - 1);
    const float* kp = k + (size_t)b * DIM * NPTS + (size_t)d * NPTS;
    const float* iv = g_invk + b * NPTS;
    float s = 0.f;
    for (int n = threadIdx.x; n < NPTS; n += 256)
        s += kp[n] * iv[n];
    __shared__ float red[8];
#pragma unroll
    for (int o = 16; o; o >>= 1) s += __shfl_down_sync(0xffffffffu, s, o);
    if ((threadIdx.x & 31) == 0) red[threadIdx.x >> 5] = s;
    __syncthreads();
    if (threadIdx.x < 8) {
        float v = red[threadIdx.x];
#pragma unroll
        for (int o = 4; o; o >>= 1) v += __shfl_down_sync(0xffu, v, o);
        if (threadIdx.x == 0) g_sumk[bd] = v;
    }
}

// ---------------------------------------------------------------------------
// K2: M2 partials. M2[b] = sum_m kn[:,m] kn[:,m]^T  (kn = L1-normalized k).
// Block = (chunk of 128 m, batch). Thread tile: 16(d1) x 4(d2) registers.
// Thread layout: ty = tid/32 (8), tx = tid%32 (32). d1 = ty*16+i, d2 = tx*4+j.
// ---------------------------------------------------------------------------
__global__ __launch_bounds__(256) void k_m2part(const float* __restrict__ k) {
    __shared__ float ks[32][132];        // [m][d], pad 132 keeps 16B row align
    int chunk = blockIdx.x, b = blockIdx.y;
    int m0 = chunk * MPERCHUNK;
    int tid = threadIdx.x;
    int ty = tid >> 5, tx = tid & 31;
    const float* kb = k + (size_t)b * DIM * NPTS;
    const float* iv = g_invk + b * NPTS + m0;

    float acc[64];
#pragma unroll
    for (int i = 0; i < 64; i++) acc[i] = 0.f;

    for (int ms = 0; ms < MPERCHUNK; ms += 32) {
        __syncthreads();
        // stage 32 m-columns, normalized, transposed to [m][d]
        int j = tid & 31;
        int dbase = (tid >> 5) * 16;
        float w = iv[ms + j];
#pragma unroll
        for (int dd = 0; dd < 16; dd++)
            ks[j][dbase + dd] = kb[(size_t)(dbase + dd) * NPTS + m0 + ms + j] * w;
        __syncthreads();

#pragma unroll 2
        for (int j2 = 0; j2 < 32; j2++) {
            const float* row = &ks[j2][0];
            float4 bv = *reinterpret_cast<const float4*>(row + tx * 4);
#pragma unroll
            for (int i4 = 0; i4 < 4; i4++) {
                float4 av = *reinterpret_cast<const float4*>(row + ty * 16 + i4 * 4);
                int ib = i4 * 16;
                acc[ib + 0]  += av.x * bv.x; acc[ib + 1]  += av.x * bv.y;
                acc[ib + 2]  += av.x * bv.z; acc[ib + 3]  += av.x * bv.w;
                acc[ib + 4]  += av.y * bv.x; acc[ib + 5]  += av.y * bv.y;
                acc[ib + 6]  += av.y * bv.z; acc[ib + 7]  += av.y * bv.w;
                acc[ib + 8]  += av.z * bv.x; acc[ib + 9]  += av.z * bv.y;
                acc[ib + 10] += av.z * bv.z; acc[ib + 11] += av.z * bv.w;
                acc[ib + 12] += av.w * bv.x; acc[ib + 13] += av.w * bv.y;
                acc[ib + 14] += av.w * bv.z; acc[ib + 15] += av.w * bv.w;
            }
        }
    }
    float* out = g_m2part + ((size_t)b * MCHUNKS + chunk) * DIM * DIM;
#pragma unroll
    for (int i = 0; i < 16; i++) {
        float4 v = make_float4(acc[i*4+0], acc[i*4+1], acc[i*4+2], acc[i*4+3]);
        *reinterpret_cast<float4*>(&out[(ty * 16 + i) * DIM + tx * 4]) = v;
    }
}

// ---------------------------------------------------------------------------
// K3: reduce M2 partials over chunks.
// ---------------------------------------------------------------------------
__global__ __launch_bounds__(256) void k_m2reduce() {
    int i = blockIdx.x * blockDim.x + threadIdx.x;   // 0..65535
    int b = i >> 14;
    int e = i & (DIM * DIM - 1);
    const float* p = g_m2part + (size_t)b * MCHUNKS * DIM * DIM + e;
    float s = 0.f;
#pragma unroll
    for (int c = 0; c < MCHUNKS; c++) s += p[(size_t)c * DIM * DIM];
    g_m2[i] = s;
}

// ---------------------------------------------------------------------------
// K4: per-row terms + row loss. Block = (32 rows, batch).
//   s1  = q . sumk            (= sum_m sim)
//   s2  = q^T M2 q            (= sum_m sim^2)
//   dg  = q . k_n             (diag term, excluded from the sum)
//   sumexp = (N-1) + (s1-dg)/T + (s2-dg^2)/(2T^2);  row loss = log(1+sumexp)
// Warp w owns rows 4w..4w+3; lane = row*8 + colgroup (8 lanes x 16 d2 each).
// ---------------------------------------------------------------------------
#define K4_SMEM_FLOATS (DIM*DIM + 32*129 + 32*129 + DIM + 32)
__global__ __launch_bounds__(256, 2) void k_rows(const float* __restrict__ q,
                                                 const float* __restrict__ k) {
    extern __shared__ float sm[];
    float* M2s   = sm;                    // 128*128
    float* qs    = M2s + DIM * DIM;       // 32*129 (padded, conflict-free)
    float* kss   = qs + 32 * 129;         // 32*129
    float* sumks = kss + 32 * 129;        // 128
    float* rloss = sumks + DIM;           // 32

    int b  = blockIdx.y;
    int n0 = blockIdx.x * 32;
    int tid = threadIdx.x;

    // load M2 tile for this batch (64 KB, coalesced float4)
    const float4* m2g = reinterpret_cast<const float4*>(g_m2 + (size_t)b * DIM * DIM);
    float4* m2s4 = reinterpret_cast<float4*>(M2s);
    for (int i = tid; i < DIM * DIM / 4; i += 256) m2s4[i] = m2g[i];
    if (tid < DIM) sumks[tid] = g_sumk[b * DIM + tid];

    // stage 32 normalized q rows and k rows, transposed to [n][d]
    {
        int j = tid & 31;
        int dbase = (tid >> 5) * 16;
        float wq = g_invq[b * NPTS + n0 + j];
        float wk = g_invk[b * NPTS + n0 + j];
        const float* qb = q + (size_t)b * DIM * NPTS + n0 + j;
        const float* kb = k + (size_t)b * DIM * NPTS + n0 + j;
#pragma unroll
        for (int dd = 0; dd < 16; dd++) {
            qs[j * 129 + dbase + dd]  = qb[(size_t)(dbase + dd) * NPTS] * wq;
            kss[j * 129 + dbase + dd] = kb[(size_t)(dbase + dd) * NPTS] * wk;
        }
    }
    __syncthreads();

    int lane = tid & 31;
    int r = (tid >> 5) * 4 + (lane >> 3);  // row 0..31
    int c = lane & 7;                       // colgroup 0..7 (16 d2 each)
    const float* qrow = qs + r * 129;

    float acc[16];
#pragma unroll
    for (int i = 0; i < 16; i++) acc[i] = 0.f;

#pragma unroll 2
    for (int d1 = 0; d1 < DIM; d1++) {
        float qv = qrow[d1];
        const float4* m2r = reinterpret_cast<const float4*>(M2s + d1 * DIM + c * 16);
        float4 v0 = m2r[0], v1 = m2r[1], v2 = m2r[2], v3 = m2r[3];
        acc[0]  += qv * v0.x; acc[1]  += qv * v0.y; acc[2]  += qv * v0.z; acc[3]  += qv * v0.w;
        acc[4]  += qv * v1.x; acc[5]  += qv * v1.y; acc[6]  += qv * v1.z; acc[7]  += qv * v1.w;
        acc[8]  += qv * v2.x; acc[9]  += qv * v2.y; acc[10] += qv * v2.z; acc[11] += qv * v2.w;
        acc[12] += qv * v3.x; acc[13] += qv * v3.y; acc[14] += qv * v3.z; acc[15] += qv * v3.w;
    }

    float s2 = 0.f, s1 = 0.f, dg = 0.f;
#pragma unroll
    for (int jj = 0; jj < 16; jj++) {
        float qv = qrow[c * 16 + jj];
        s2 += acc[jj] * qv;
        s1 += qv * sumks[c * 16 + jj];
        dg += qv * kss[r * 129 + c * 16 + jj];
    }
#pragma unroll
    for (int o = 1; o < 8; o <<= 1) {
        s2 += __shfl_xor_sync(0xffffffffu, s2, o);
        s1 += __shfl_xor_sync(0xffffffffu, s1, o);
        dg += __shfl_xor_sync(0xffffffffu, dg, o);
    }
    if (c == 0) {
        float a1 = (s1 - dg) * INV_T;
        float a2 = (s2 - dg * dg) * (INV_T * INV_T * 0.5f);
        float sumexp = (float)(NPTS - 1) + a1 + a2;
        rloss[r] = logf(1.0f + sumexp);     // = logaddexp(0, lse)
    }
    __syncthreads();
    if (tid == 0) {
        float t = 0.f;
#pragma unroll
        for (int i = 0; i < 32; i++) t += rloss[i];
        g_rowpart[blockIdx.y * gridDim.x + blockIdx.x] = t;
    }
}

// ---------------------------------------------------------------------------
// K5: final deterministic reduction of 512 block partials -> mean loss.
// ---------------------------------------------------------------------------
__global__ __launch_bounds__(512) void k_final(float* __restrict__ out) {
    __shared__ float red[512];
    red[threadIdx.x] = g_rowpart[threadIdx.x];
    __syncthreads();
#pragma unroll
    for (int s = 256; s > 0; s >>= 1) {
        if (threadIdx.x < s) red[threadIdx.x] += red[threadIdx.x + s];
        __syncthreads();
    }
    if (threadIdx.x == 0) out[0] = red[0] * (1.0f / (float)NB);
}

// ---------------------------------------------------------------------------
extern "C" void kernel_launch(void* const* d_in, const int* in_sizes, int n_in,
                              void* d_out, int out_size) {
    const float* q = (const float*)d_in[0];
    const float* k = (const float*)d_in[1];
    float* out = (float*)d_out;
    (void)in_sizes; (void)n_in; (void)out_size;

    static const int k4_smem = K4_SMEM_FLOATS * (int)sizeof(float);  // ~97 KB
    cudaFuncSetAttribute(k_rows, cudaFuncAttributeMaxDynamicSharedMemorySize, k4_smem);

    k_norms<<<NB / 256, 256>>>(q, k);
    k_sumk<<<BATCH * DIM, 256>>>(k);
    k_m2part<<<dim3(MCHUNKS, BATCH), 256>>>(k);
    k_m2reduce<<<BATCH * DIM * DIM / 256, 256>>>();
    k_rows<<<dim3(NPTS / 32, BATCH), 256, k4_smem>>>(q, k);
    k_final<<<1, 512>>>(out);
}

// round 2
// speedup vs baseline: 4.1685x; 4.1685x over previous
#include <cuda_runtime.h>
#include <math.h>

#define BATCH 4
#define DIM   128
#define NPTS  4096
#define NB    (BATCH*NPTS)          // 16384 rows total
#define INV_T 14.285714285714286f   // 1/0.07
#define MCHUNKS 32
#define MPER  (NPTS/MCHUNKS)        // 128 m-rows per gram block

// ---- device scratch (no allocations allowed) ----
__device__ float g_invq[NB];
__device__ float g_invk[NB];
__device__ float g_dgpart[128];
__device__ float g_dg2part[128];
__device__ float g_gpart[(size_t)2*BATCH*MCHUNKS*DIM*DIM]; // 16 MB gram partials
__device__ float g_spart[2*BATCH*MCHUNKS*DIM];             // column-sum partials
__device__ float g_fpart[BATCH*64];                        // frobenius partials

// ---- f32x2 packed-FMA helpers (sm_103a FFMA2 — only reachable via PTX) ----
__device__ __forceinline__ unsigned long long bcast2(float v) {
    unsigned long long r;
    asm("mov.b64 %0, {%1, %1};" : "=l"(r) : "f"(v));
    return r;
}
__device__ __forceinline__ void ffma2(unsigned long long& acc,
                                      unsigned long long a, unsigned long long b) {
    asm("fma.rn.f32x2 %0, %1, %2, %0;" : "+l"(acc) : "l"(a), "l"(b));
}
__device__ __forceinline__ float2 unpk2(unsigned long long v) {
    float2 r;
    asm("mov.b64 {%0, %1}, %2;" : "=f"(r.x), "=f"(r.y) : "l"(v));
    return r;
}

// ---------------------------------------------------------------------------
// K1: fused prologue. Per row (b,n): L1 norms of q,k AND the q.k dot in ONE
// pass over d. Stores inv norms; block-reduces sum(dg) and sum(dg^2).
// ---------------------------------------------------------------------------
__global__ __launch_bounds__(128) void k_prologue(const float* __restrict__ q,
                                                  const float* __restrict__ k) {
    int t = blockIdx.x * 128 + threadIdx.x;     // 0..16383
    int b = t >> 12;
    int n = t & (NPTS - 1);
    const float* qp = q + (size_t)b * DIM * NPTS + n;
    const float* kp = k + (size_t)b * DIM * NPTS + n;
    float sq = 0.f, sk = 0.f, dot = 0.f;
#pragma unroll 16
    for (int d = 0; d < DIM; d++) {
        float qv = qp[(size_t)d * NPTS];
        float kv = kp[(size_t)d * NPTS];
        sq += fabsf(qv);
        sk += fabsf(kv);
        dot += qv * kv;
    }
    float iq = 1.0f / fmaxf(sq, 1e-12f);
    float ik = 1.0f / fmaxf(sk, 1e-12f);
    g_invq[t] = iq;
    g_invk[t] = ik;
    float dg = dot * iq * ik;
    float dg2 = dg * dg;

    __shared__ float r1[4], r2[4];
#pragma unroll
    for (int o = 16; o; o >>= 1) {
        dg  += __shfl_down_sync(0xffffffffu, dg, o);
        dg2 += __shfl_down_sync(0xffffffffu, dg2, o);
    }
    if ((threadIdx.x & 31) == 0) { r1[threadIdx.x >> 5] = dg; r2[threadIdx.x >> 5] = dg2; }
    __syncthreads();
    if (threadIdx.x == 0) {
        g_dgpart[blockIdx.x]  = r1[0] + r1[1] + r1[2] + r1[3];
        g_dg2part[blockIdx.x] = r2[0] + r2[1] + r2[2] + r2[3];
    }
}

// ---------------------------------------------------------------------------
// K2: Gram partials. block = (chunk c, batch b, which w: 0=q,1=k).
// G[w][b] += sum over 128 m of xn[:,m] xn[:,m]^T.
// Thread tile 16(d1) x 4(d2), accumulated as f32x2 pairs along d1.
// Also accumulates column sums (sum over m of xn[d][m]) for s1.
// ---------------------------------------------------------------------------
__global__ __launch_bounds__(256, 2) void k_gram(const float* __restrict__ q,
                                                 const float* __restrict__ k) {
    __shared__ float ks[32][132];    // [m][d], pad keeps 16B row alignment
    int c = blockIdx.x, b = blockIdx.y, w = blockIdx.z;
    const float* x    = w ? k : q;
    const float* invg = w ? g_invk : g_invq;
    int m0 = c * MPER;
    int tid = threadIdx.x;
    int ty = tid >> 5, tx = tid & 31;       // warp = fixed ty (d1 group)
    const float* xb = x + (size_t)b * DIM * NPTS;
    const float* iv = invg + b * NPTS + m0;

    unsigned long long acc2[32];            // [p 0..7][jj 0..3]: d1 pair x d2
#pragma unroll
    for (int i = 0; i < 32; i++) acc2[i] = 0ull;
    float csum[16];
#pragma unroll
    for (int i = 0; i < 16; i++) csum[i] = 0.f;

    int j = tx;                 // m within stage
    int dbase = ty * 16;
    for (int ms = 0; ms < MPER; ms += 32) {
        __syncthreads();
        float wgt = iv[ms + j];
#pragma unroll
        for (int dd = 0; dd < 16; dd++) {
            float v = xb[(size_t)(dbase + dd) * NPTS + m0 + ms + j] * wgt;
            ks[j][dbase + dd] = v;
            csum[dd] += v;
        }
        __syncthreads();
#pragma unroll 4
        for (int m = 0; m < 32; m++) {
            const float* row = &ks[m][0];
            float4 bv = *reinterpret_cast<const float4*>(row + tx * 4);
            unsigned long long b0 = bcast2(bv.x), b1 = bcast2(bv.y);
            unsigned long long b2 = bcast2(bv.z), b3 = bcast2(bv.w);
            const ulonglong2* ap = reinterpret_cast<const ulonglong2*>(row + ty * 16);
            ulonglong2 a01 = ap[0], a23 = ap[1], a45 = ap[2], a67 = ap[3];
            unsigned long long av[8] = {a01.x, a01.y, a23.x, a23.y,
                                        a45.x, a45.y, a67.x, a67.y};
#pragma unroll
            for (int p = 0; p < 8; p++) {
                ffma2(acc2[p * 4 + 0], av[p], b0);
                ffma2(acc2[p * 4 + 1], av[p], b1);
                ffma2(acc2[p * 4 + 2], av[p], b2);
                ffma2(acc2[p * 4 + 3], av[p], b3);
            }
        }
    }

    // write gram partial tile (coalesced float4)
    float* out = g_gpart + (((size_t)(w * BATCH + b) * MCHUNKS + c) * DIM * DIM);
#pragma unroll
    for (int p = 0; p < 8; p++) {
        float2 u0 = unpk2(acc2[p * 4 + 0]);
        float2 u1 = unpk2(acc2[p * 4 + 1]);
        float2 u2 = unpk2(acc2[p * 4 + 2]);
        float2 u3 = unpk2(acc2[p * 4 + 3]);
        *reinterpret_cast<float4*>(&out[(dbase + 2 * p) * DIM + tx * 4]) =
            make_float4(u0.x, u1.x, u2.x, u3.x);
        *reinterpret_cast<float4*>(&out[(dbase + 2 * p + 1) * DIM + tx * 4]) =
            make_float4(u0.y, u1.y, u2.y, u3.y);
    }

    // column-sum partials: warp has fixed dbase, lanes cover all 32 m of a stage
    float* sout = g_spart + ((w * BATCH + b) * MCHUNKS + c) * DIM + dbase;
#pragma unroll
    for (int dd = 0; dd < 16; dd++) {
        float v = csum[dd];
#pragma unroll
        for (int o = 16; o; o >>= 1) v += __shfl_down_sync(0xffffffffu, v, o);
        if (tx == 0) sout[dd] = v;
    }
}

// ---------------------------------------------------------------------------
// K3: reduce gram partials over chunks and form Frobenius product partials.
// ---------------------------------------------------------------------------
__global__ __launch_bounds__(256) void k_frob() {
    int b = blockIdx.y;
    int e = blockIdx.x * 256 + threadIdx.x;   // 0..16383 within the 128x128 gram
    const float* pq = g_gpart + (size_t)(0 * BATCH + b) * MCHUNKS * DIM * DIM + e;
    const float* pk = g_gpart + (size_t)(1 * BATCH + b) * MCHUNKS * DIM * DIM + e;
    float gq = 0.f, gk = 0.f;
#pragma unroll
    for (int c = 0; c < MCHUNKS; c++) {
        gq += pq[(size_t)c * DIM * DIM];
        gk += pk[(size_t)c * DIM * DIM];
    }
    float f = gq * gk;
    __shared__ float r[8];
#pragma unroll
    for (int o = 16; o; o >>= 1) f += __shfl_down_sync(0xffffffffu, f, o);
    if ((threadIdx.x & 31) == 0) r[threadIdx.x >> 5] = f;
    __syncthreads();
    if (threadIdx.x < 8) {
        float v = r[threadIdx.x];
#pragma unroll
        for (int o = 4; o; o >>= 1) v += __shfl_down_sync(0xffu, v, o);
        if (threadIdx.x == 0) g_fpart[b * 64 + blockIdx.x] = v;
    }
}

// ---------------------------------------------------------------------------
// K4: combine everything into the scalar loss.
// loss = log(N) + [ (1/T)(Sum s1 - Sum dg) + (1/(2T^2))(Sum F - Sum dg^2) ] / (N*NB)
// ---------------------------------------------------------------------------
__global__ __launch_bounds__(256) void k_loss(float* __restrict__ out) {
    __shared__ float red[256];
    int tid = threadIdx.x;

    float f = g_fpart[tid];   // exactly 256 frobenius partials

    // S1: per (b,d): (sum_c sq)(sum_c sk); 512 pairs, 2 per thread
    float s1 = 0.f;
    for (int i = tid; i < 2 * BATCH * DIM / 2; i += 256) {
        int b = i >> 7, d = i & 127;
        float sq = 0.f, sk = 0.f;
#pragma unroll
        for (int c = 0; c < MCHUNKS; c++) {
            sq += g_spart[((0 * BATCH + b) * MCHUNKS + c) * DIM + d];
            sk += g_spart[((1 * BATCH + b) * MCHUNKS + c) * DIM + d];
        }
        s1 += sq * sk;
    }

    float dg = 0.f, dg2 = 0.f;
    if (tid < 128) { dg = g_dgpart[tid]; dg2 = g_dg2part[tid]; }

    const float halfT2 = 0.5f * INV_T * INV_T;
    red[tid] = INV_T * (s1 - dg) + halfT2 * (f - dg2);
    __syncthreads();
#pragma unroll
    for (int s = 128; s; s >>= 1) {
        if (tid < s) red[tid] += red[tid + s];
        __syncthreads();
    }
    if (tid == 0)
        out[0] = logf((float)NPTS) + red[0] / ((float)NPTS * (float)NB);
}

// ---------------------------------------------------------------------------
extern "C" void kernel_launch(void* const* d_in, const int* in_sizes, int n_in,
                              void* d_out, int out_size) {
    const float* q = (const float*)d_in[0];
    const float* k = (const float*)d_in[1];
    float* out = (float*)d_out;
    (void)in_sizes; (void)n_in; (void)out_size;

    k_prologue<<<NB / 128, 128>>>(q, k);
    k_gram<<<dim3(MCHUNKS, BATCH, 2), 256>>>(q, k);
    k_frob<<<dim3(DIM * DIM / 256, BATCH), 256>>>();
    k_loss<<<1, 256>>>(out);
}

// round 4
// speedup vs baseline: 8.9392x; 2.1445x over previous
#include <cuda_runtime.h>
#include <cuda_bf16.h>
#include <cstdint>
#include <math.h>

#define BATCH 4
#define DIM   128
#define NPTS  4096
#define NB    (BATCH*NPTS)
#define MC    32            // m-chunks
#define MPER  128           // m per chunk
#define NBLK  (MC*BATCH)
#define INV_T 14.285714285714286f

// ---- device scratch (no allocations allowed) ----
__device__ float g_gpart[(size_t)2*BATCH*MC*DIM*DIM]; // 16 MB gram partials
__device__ float g_spart[2*BATCH*MC*DIM];             // column-sum partials
__device__ float g_dgpart[NBLK];
__device__ float g_dg2part[NBLK];
__device__ float g_fpart[BATCH*64];
__device__ float g_s1[BATCH];

// =============================== PTX helpers ===============================
__device__ __forceinline__ uint32_t smem_u32(const void* p) {
    uint32_t a;
    asm("{ .reg .u64 t; cvta.to.shared.u64 t, %1; cvt.u32.u64 %0, t; }"
        : "=r"(a) : "l"(p));
    return a;
}
__device__ __forceinline__ void ldsm_x4(uint32_t* r, uint32_t addr) {
    asm volatile("ldmatrix.sync.aligned.m8n8.x4.shared.b16 {%0,%1,%2,%3}, [%4];"
        : "=r"(r[0]), "=r"(r[1]), "=r"(r[2]), "=r"(r[3]) : "r"(addr));
}
__device__ __forceinline__ void mma_bf16(float* c, const uint32_t* a,
                                         uint32_t b0, uint32_t b1) {
    asm volatile("mma.sync.aligned.m16n8k16.row.col.f32.bf16.bf16.f32 "
        "{%0,%1,%2,%3}, {%4,%5,%6,%7}, {%8,%9}, {%0,%1,%2,%3};"
        : "+f"(c[0]), "+f"(c[1]), "+f"(c[2]), "+f"(c[3])
        : "r"(a[0]), "r"(a[1]), "r"(a[2]), "r"(a[3]), "r"(b0), "r"(b1));
}

// bf16 tile: [128 d rows][136 m cols] (272 B row stride, conflict-free LDSM)
#define BSTRIDE 272

// smem byte offsets
#define SB_QF 0
#define SB_KF 65536
#define SB_QB 131072          // 128*272 = 34816 B
#define SB_KB 165888
#define SB_IQ 200704
#define SB_IK 201216
#define SB_R1 201728
#define SB_R2 202752
#define SB_R3 203776
#define SB_TOTAL 204800

// ===========================================================================
// k_main: per (chunk,b): load q/k fp32 tiles, column L1 norms + q.k (dg),
// normalize->bf16, two tensor-core Grams via mma.sync, write partials.
// ===========================================================================
__global__ __launch_bounds__(256, 1) void k_main(const float* __restrict__ q,
                                                 const float* __restrict__ k) {
    extern __shared__ char smc[];
    float* qf = (float*)(smc + SB_QF);
    float* kf = (float*)(smc + SB_KF);
    char*  qb = smc + SB_QB;
    char*  kb = smc + SB_KB;
    float* iq = (float*)(smc + SB_IQ);
    float* ik = (float*)(smc + SB_IK);
    float* r1 = (float*)(smc + SB_R1);
    float* r2 = (float*)(smc + SB_R2);
    float* r3 = (float*)(smc + SB_R3);

    int tid = threadIdx.x, wid = tid >> 5, lane = tid & 31;
    int cblk = blockIdx.x, b = blockIdx.y;
    int m0 = cblk * MPER;

    // ---- load q/k fp32 tiles (coalesced float4; input read exactly once) --
    const float* qg = q + (size_t)b * DIM * NPTS + m0;
    const float* kg = k + (size_t)b * DIM * NPTS + m0;
#pragma unroll
    for (int it = 0; it < 16; it++) {
        int d = it * 8 + wid;
        float4 vq = *(const float4*)(qg + (size_t)d * NPTS + lane * 4);
        float4 vk = *(const float4*)(kg + (size_t)d * NPTS + lane * 4);
        *(float4*)(qf + d * 128 + lane * 4) = vq;
        *(float4*)(kf + d * 128 + lane * 4) = vk;
    }
    __syncthreads();

    // ---- column L1 norms + q.k dot ---------------------------------------
    {
        int m = tid & 127, h = tid >> 7;
        const float* qp = qf + h * 64 * 128 + m;
        const float* kp = kf + h * 64 * 128 + m;
        float sq = 0.f, sk = 0.f, dot = 0.f;
#pragma unroll 8
        for (int d = 0; d < 64; d++) {
            float a = qp[d * 128], e = kp[d * 128];
            sq += fabsf(a); sk += fabsf(e); dot += a * e;
        }
        r1[tid] = sq; r2[tid] = sk; r3[tid] = dot;
    }
    __syncthreads();
    if (tid < 128) {
        float sq = r1[tid] + r1[tid + 128];
        float sk = r2[tid] + r2[tid + 128];
        float dt = r3[tid] + r3[tid + 128];
        float iqv = 1.f / fmaxf(sq, 1e-12f);
        float ikv = 1.f / fmaxf(sk, 1e-12f);
        iq[tid] = iqv; ik[tid] = ikv;
        float dg = dt * iqv * ikv;
        float dg2 = dg * dg;
#pragma unroll
        for (int o = 16; o; o >>= 1) {
            dg  += __shfl_down_sync(0xffffffffu, dg, o);
            dg2 += __shfl_down_sync(0xffffffffu, dg2, o);
        }
        if (lane == 0) { r3[wid] = dg; r3[8 + wid] = dg2; }
    }
    __syncthreads();
    if (tid == 0) {
        int blk = b * MC + cblk;
        g_dgpart[blk]  = r3[0] + r3[1] + r3[2] + r3[3];
        g_dg2part[blk] = r3[8] + r3[9] + r3[10] + r3[11];
    }

    // ---- normalize -> bf16 (padded rows) + column sums --------------------
    float* sqout = g_spart + ((0 * BATCH + b) * MC + cblk) * DIM;
    float* skout = g_spart + ((1 * BATCH + b) * MC + cblk) * DIM;
    {
        int m4 = lane * 4;
        float4 iqv = *(float4*)(iq + m4);
        float4 ikv = *(float4*)(ik + m4);
#pragma unroll
        for (int it = 0; it < 16; it++) {
            int d = it * 8 + wid;
            float4 vq = *(float4*)(qf + d * 128 + m4);
            float4 vk = *(float4*)(kf + d * 128 + m4);
            float q0 = vq.x * iqv.x, q1 = vq.y * iqv.y,
                  q2 = vq.z * iqv.z, q3 = vq.w * iqv.w;
            float k0 = vk.x * ikv.x, k1 = vk.y * ikv.y,
                  k2 = vk.z * ikv.z, k3 = vk.w * ikv.w;
            __nv_bfloat162 a01 = __float22bfloat162_rn(make_float2(q0, q1));
            __nv_bfloat162 a23 = __float22bfloat162_rn(make_float2(q2, q3));
            __nv_bfloat162 e01 = __float22bfloat162_rn(make_float2(k0, k1));
            __nv_bfloat162 e23 = __float22bfloat162_rn(make_float2(k2, k3));
            uint2 qpk = make_uint2(*(uint32_t*)&a01, *(uint32_t*)&a23);
            uint2 kpk = make_uint2(*(uint32_t*)&e01, *(uint32_t*)&e23);
            uint32_t off = (uint32_t)(d * BSTRIDE + lane * 8);
            *(uint2*)(qb + off) = qpk;
            *(uint2*)(kb + off) = kpk;
            float cs = (q0 + q1) + (q2 + q3);
            float ck = (k0 + k1) + (k2 + k3);
#pragma unroll
            for (int o = 16; o; o >>= 1) {
                cs += __shfl_down_sync(0xffffffffu, cs, o);
                ck += __shfl_down_sync(0xffffffffu, ck, o);
            }
            if (lane == 0) { sqout[d] = cs; skout[d] = ck; }
        }
    }
    __syncthreads();

    // ---- tensor-core Grams: G = Xn[128d x 128m] * Xn^T --------------------
    // A row-major [d1][m] and B col-major [m][d2] share the same [d][m] tile:
    // both fragments load with plain (non-trans) ldmatrix.
    uint32_t qb_u32 = smem_u32(qb);
    uint32_t kb_u32 = smem_u32(kb);
    int grp = lane >> 3;
    int arow = (wid << 4) + ((grp & 1) << 3) + (lane & 7);
    uint32_t a_off = (uint32_t)(arow * BSTRIDE + ((grp >> 1) << 4));
    int brow = ((grp >> 1) << 3) + (lane & 7);
    uint32_t b_off = (uint32_t)(brow * BSTRIDE + ((grp & 1) << 4));

    int r  = lane >> 2;
    int cp = (lane & 3) << 1;
    int d1r = (wid << 4) + r;

#pragma unroll
    for (int which = 0; which < 2; which++) {
        uint32_t base = which ? kb_u32 : qb_u32;
        uint32_t abase = base + a_off;
        uint32_t bbase = base + b_off;
        float c[64];
#pragma unroll
        for (int i = 0; i < 64; i++) c[i] = 0.f;

#pragma unroll
        for (int ks = 0; ks < 8; ks++) {
            uint32_t a[4];
            ldsm_x4(a, abase + ks * 32);
#pragma unroll
            for (int bt = 0; bt < 8; bt++) {
                uint32_t bb[4];
                ldsm_x4(bb, bbase + (uint32_t)(bt * 16 * BSTRIDE) + ks * 32);
                mma_bf16(c + bt * 8,     a, bb[0], bb[1]);
                mma_bf16(c + bt * 8 + 4, a, bb[2], bb[3]);
            }
        }

        float* outp = g_gpart
            + (((size_t)(which * BATCH + b) * MC + cblk) * DIM * DIM);
#pragma unroll
        for (int bt = 0; bt < 8; bt++) {
#pragma unroll
            for (int h = 0; h < 2; h++) {
                int nt = bt * 2 + h;
                const float* cc = c + bt * 8 + h * 4;
                float* p0 = outp + (size_t)d1r * DIM + nt * 8 + cp;
                *(float2*)p0 = make_float2(cc[0], cc[1]);
                *(float2*)(p0 + 8 * DIM) = make_float2(cc[2], cc[3]);
            }
        }
    }
}

// ===========================================================================
// k_red: blockIdx.x<64 -> Frobenius partials; ==64 -> s1 per batch.
// ===========================================================================
__global__ __launch_bounds__(256) void k_red() {
    __shared__ float rr[8];
    __shared__ float sq[DIM], sk[DIM];
    int b = blockIdx.y;
    int tid = threadIdx.x;

    if (blockIdx.x < 64) {
        int e = blockIdx.x * 256 + tid;
        const float* pq = g_gpart + (size_t)(0 * BATCH + b) * MC * DIM * DIM + e;
        const float* pk = g_gpart + (size_t)(1 * BATCH + b) * MC * DIM * DIM + e;
        float gq = 0.f, gk = 0.f;
#pragma unroll
        for (int c = 0; c < MC; c++) {
            gq += pq[(size_t)c * DIM * DIM];
            gk += pk[(size_t)c * DIM * DIM];
        }
        float f = gq * gk;
#pragma unroll
        for (int o = 16; o; o >>= 1) f += __shfl_down_sync(0xffffffffu, f, o);
        if ((tid & 31) == 0) rr[tid >> 5] = f;
        __syncthreads();
        if (tid == 0) {
            float t = 0.f;
#pragma unroll
            for (int i = 0; i < 8; i++) t += rr[i];
            g_fpart[b * 64 + blockIdx.x] = t;
        }
    } else {
        int w = tid >> 7, d = tid & 127;
        const float* p = g_spart + ((w * BATCH + b) * MC) * DIM + d;
        float s = 0.f;
#pragma unroll
        for (int c = 0; c < MC; c++) s += p[c * DIM];
        if (w == 0) sq[d] = s; else sk[d] = s;
        __syncthreads();
        if (tid < 128) {
            float v = sq[d] * sk[d];
#pragma unroll
            for (int o = 16; o; o >>= 1) v += __shfl_down_sync(0xffffffffu, v, o);
            if ((tid & 31) == 0) rr[tid >> 5] = v;
        }
        __syncthreads();
        if (tid == 0) g_s1[b] = rr[0] + rr[1] + rr[2] + rr[3];
    }
}

// ===========================================================================
// k_loss: combine into scalar.
// loss = log(N) + [ (1/T)(s1 - sum dg) + (1/(2T^2))(F - sum dg^2) ] / (N*NB)
// ===========================================================================
__global__ __launch_bounds__(256) void k_loss(float* __restrict__ out) {
    __shared__ float red[256];
    int tid = threadIdx.x;
    const float halfT2 = 0.5f * INV_T * INV_T;
    float v = halfT2 * g_fpart[tid];
    if (tid < BATCH) v += INV_T * g_s1[tid];
    if (tid < NBLK)  v -= INV_T * g_dgpart[tid] + halfT2 * g_dg2part[tid];
    red[tid] = v;
    __syncthreads();
#pragma unroll
    for (int s = 128; s; s >>= 1) {
        if (tid < s) red[tid] += red[tid + s];
        __syncthreads();
    }
    if (tid == 0)
        out[0] = logf((float)NPTS) + red[0] / ((float)NPTS * (float)NB);
}

// ===========================================================================
extern "C" void kernel_launch(void* const* d_in, const int* in_sizes, int n_in,
                              void* d_out, int out_size) {
    const float* q = (const float*)d_in[0];
    const float* k = (const float*)d_in[1];
    float* out = (float*)d_out;
    (void)in_sizes; (void)n_in; (void)out_size;

    cudaFuncSetAttribute(k_main, cudaFuncAttributeMaxDynamicSharedMemorySize,
                         SB_TOTAL);

    k_main<<<dim3(MC, BATCH), 256, SB_TOTAL>>>(q, k);
    k_red<<<dim3(65, BATCH), 256>>>();
    k_loss<<<1, 256>>>(out);
}

// round 5
// speedup vs baseline: 9.1959x; 1.0287x over previous
#include <cuda_runtime.h>
#include <cuda_bf16.h>
#include <cstdint>
#include <math.h>

#define BATCH 4
#define DIM   128
#define NPTS  4096
#define NB    (BATCH*NPTS)
#define MC    32            // m-chunks
#define MPER  128           // m per chunk
#define NBLK  (MC*BATCH)
#define INV_T 14.285714285714286f

// ---- device scratch (no allocations allowed) ----
__device__ float g_gpart[(size_t)2*BATCH*MC*DIM*DIM]; // 16 MB gram partials
__device__ float g_spart[2*BATCH*MC*DIM];             // column-sum partials
__device__ float g_dgpart[NBLK];
__device__ float g_dg2part[NBLK];
__device__ float g_fpart[BATCH*64];
__device__ float g_s1[BATCH];

// =============================== PTX helpers ===============================
__device__ __forceinline__ uint32_t smem_u32(const void* p) {
    uint32_t a;
    asm("{ .reg .u64 t; cvta.to.shared.u64 t, %1; cvt.u32.u64 %0, t; }"
        : "=r"(a) : "l"(p));
    return a;
}
__device__ __forceinline__ void ldsm_x4(uint32_t* r, uint32_t addr) {
    asm volatile("ldmatrix.sync.aligned.m8n8.x4.shared.b16 {%0,%1,%2,%3}, [%4];"
        : "=r"(r[0]), "=r"(r[1]), "=r"(r[2]), "=r"(r[3]) : "r"(addr));
}
__device__ __forceinline__ void mma_bf16(float* c, const uint32_t* a,
                                         uint32_t b0, uint32_t b1) {
    asm volatile("mma.sync.aligned.m16n8k16.row.col.f32.bf16.bf16.f32 "
        "{%0,%1,%2,%3}, {%4,%5,%6,%7}, {%8,%9}, {%0,%1,%2,%3};"
        : "+f"(c[0]), "+f"(c[1]), "+f"(c[2]), "+f"(c[3])
        : "r"(a[0]), "r"(a[1]), "r"(a[2]), "r"(a[3]), "r"(b0), "r"(b1));
}
__device__ __forceinline__ uint32_t hmul2u(uint32_t a, uint32_t b) {
    uint32_t r;
    asm("mul.bf16x2 %0, %1, %2;" : "=r"(r) : "r"(a), "r"(b));
    return r;
}

// bf16 tile: [128 d rows][136 m cols] (272 B row stride, conflict-free LDSM)
#define BSTRIDE 272

// smem byte offsets
#define SB_QB  0             // 34816
#define SB_KB  34816         // 34816
#define SB_RQ  69632         // 16 warps x 128 m x 4B = 8192
#define SB_RK  77824
#define SB_RD  86016
#define SB_IQ2 94208         // 64 x u32 packed bf16x2 inv-norms (q)
#define SB_IK2 94464
#define SB_SCR 94720         // small reduce scratch
#define SB_TOTAL 94784

// ===========================================================================
// k_main: 512 threads. Single global read; raw bf16 kept in registers; norms
// + q.k in fp32 in flight; HMUL2 normalize -> padded tile; warps 0-7 compute
// Gq gram, warps 8-15 compute Gk gram via mma.sync.
// ===========================================================================
__global__ __launch_bounds__(512, 1) void k_main(const float* __restrict__ q,
                                                 const float* __restrict__ k) {
    extern __shared__ char smc[];
    char*  qb  = smc + SB_QB;
    char*  kb  = smc + SB_KB;
    float* rq  = (float*)(smc + SB_RQ);
    float* rk  = (float*)(smc + SB_RK);
    float* rd  = (float*)(smc + SB_RD);
    uint32_t* iq2 = (uint32_t*)(smc + SB_IQ2);
    uint32_t* ik2 = (uint32_t*)(smc + SB_IK2);
    float* scr = (float*)(smc + SB_SCR);

    int tid = threadIdx.x, wid = tid >> 5, lane = tid & 31;
    int cblk = blockIdx.x, b = blockIdx.y;
    int m0 = cblk * MPER;
    int m4 = lane * 4;

    // ---- phase 1: single global read; norms/dot partials; raw bf16 in regs
    const float* qg = q + (size_t)b * DIM * NPTS + m0 + m4;
    const float* kg = k + (size_t)b * DIM * NPTS + m0 + m4;
    uint2 qr[8], kr[8];
    float sq0 = 0.f, sq1 = 0.f, sq2 = 0.f, sq3 = 0.f;
    float sk0 = 0.f, sk1 = 0.f, sk2 = 0.f, sk3 = 0.f;
    float dt0 = 0.f, dt1 = 0.f, dt2 = 0.f, dt3 = 0.f;
#pragma unroll
    for (int it = 0; it < 8; it++) {
        int d = it * 16 + wid;
        float4 vq = *(const float4*)(qg + (size_t)d * NPTS);
        float4 vk = *(const float4*)(kg + (size_t)d * NPTS);
        sq0 += fabsf(vq.x); sq1 += fabsf(vq.y); sq2 += fabsf(vq.z); sq3 += fabsf(vq.w);
        sk0 += fabsf(vk.x); sk1 += fabsf(vk.y); sk2 += fabsf(vk.z); sk3 += fabsf(vk.w);
        dt0 += vq.x * vk.x; dt1 += vq.y * vk.y; dt2 += vq.z * vk.z; dt3 += vq.w * vk.w;
        __nv_bfloat162 a01 = __float22bfloat162_rn(make_float2(vq.x, vq.y));
        __nv_bfloat162 a23 = __float22bfloat162_rn(make_float2(vq.z, vq.w));
        __nv_bfloat162 e01 = __float22bfloat162_rn(make_float2(vk.x, vk.y));
        __nv_bfloat162 e23 = __float22bfloat162_rn(make_float2(vk.z, vk.w));
        qr[it] = make_uint2(*(uint32_t*)&a01, *(uint32_t*)&a23);
        kr[it] = make_uint2(*(uint32_t*)&e01, *(uint32_t*)&e23);
    }
    *(float4*)(rq + wid * 128 + m4) = make_float4(sq0, sq1, sq2, sq3);
    *(float4*)(rk + wid * 128 + m4) = make_float4(sk0, sk1, sk2, sk3);
    *(float4*)(rd + wid * 128 + m4) = make_float4(dt0, dt1, dt2, dt3);
    __syncthreads();

    // ---- phase 2: reduce over 16 warps; inv norms; dg/dg2; pack bf16 scales
    if (tid < 128) {
        float sq = 0.f, sk = 0.f, dt = 0.f;
#pragma unroll
        for (int w = 0; w < 16; w++) {
            sq += rq[w * 128 + tid];
            sk += rk[w * 128 + tid];
            dt += rd[w * 128 + tid];
        }
        float iqv = 1.f / fmaxf(sq, 1e-12f);
        float ikv = 1.f / fmaxf(sk, 1e-12f);
        // pack bf16x2 scales for pairs (m, m+1)
        float iqh = __shfl_down_sync(0xffffffffu, iqv, 1);
        float ikh = __shfl_down_sync(0xffffffffu, ikv, 1);
        if ((tid & 1) == 0) {
            __nv_bfloat162 pq = __float22bfloat162_rn(make_float2(iqv, iqh));
            __nv_bfloat162 pk = __float22bfloat162_rn(make_float2(ikv, ikh));
            iq2[tid >> 1] = *(uint32_t*)&pq;
            ik2[tid >> 1] = *(uint32_t*)&pk;
        }
        float dg = dt * iqv * ikv;
        float dg2 = dg * dg;
#pragma unroll
        for (int o = 16; o; o >>= 1) {
            dg  += __shfl_down_sync(0xffffffffu, dg, o);
            dg2 += __shfl_down_sync(0xffffffffu, dg2, o);
        }
        if (lane == 0) { scr[wid] = dg; scr[4 + wid] = dg2; }
    }
    __syncthreads();
    if (tid == 0) {
        int blk = b * MC + cblk;
        g_dgpart[blk]  = scr[0] + scr[1] + scr[2] + scr[3];
        g_dg2part[blk] = scr[4] + scr[5] + scr[6] + scr[7];
    }

    // ---- phase 3: HMUL2 normalize regs -> tile; column sums for s1 -------
    float* sqout = g_spart + ((0 * BATCH + b) * MC + cblk) * DIM;
    float* skout = g_spart + ((1 * BATCH + b) * MC + cblk) * DIM;
    {
        uint32_t su0 = iq2[lane * 2], su1 = iq2[lane * 2 + 1];
        uint32_t tu0 = ik2[lane * 2], tu1 = ik2[lane * 2 + 1];
#pragma unroll
        for (int it = 0; it < 8; it++) {
            int d = it * 16 + wid;
            uint32_t q0 = hmul2u(qr[it].x, su0);
            uint32_t q1 = hmul2u(qr[it].y, su1);
            uint32_t k0 = hmul2u(kr[it].x, tu0);
            uint32_t k1 = hmul2u(kr[it].y, tu1);
            uint32_t off = (uint32_t)(d * BSTRIDE + lane * 8);
            *(uint2*)(qb + off) = make_uint2(q0, q1);
            *(uint2*)(kb + off) = make_uint2(k0, k1);
            float2 f0 = __bfloat1622float2(*(__nv_bfloat162*)&q0);
            float2 f1 = __bfloat1622float2(*(__nv_bfloat162*)&q1);
            float2 g0 = __bfloat1622float2(*(__nv_bfloat162*)&k0);
            float2 g1 = __bfloat1622float2(*(__nv_bfloat162*)&k1);
            float cs = (f0.x + f0.y) + (f1.x + f1.y);
            float ck = (g0.x + g0.y) + (g1.x + g1.y);
#pragma unroll
            for (int o = 16; o; o >>= 1) {
                cs += __shfl_down_sync(0xffffffffu, cs, o);
                ck += __shfl_down_sync(0xffffffffu, ck, o);
            }
            if (lane == 0) { sqout[d] = cs; skout[d] = ck; }
        }
    }
    __syncthreads();

    // ---- phase 4: grams. warps 0-7 -> Gq, warps 8-15 -> Gk ---------------
    // A row-major [d1][m] and B col-major [m][d2] share the same [d][m] tile.
    int which = wid >> 3;
    int wrow = wid & 7;
    uint32_t base = smem_u32(which ? kb : qb);
    int grp = lane >> 3;
    int arow = (wrow << 4) + ((grp & 1) << 3) + (lane & 7);
    uint32_t abase = base + (uint32_t)(arow * BSTRIDE + ((grp >> 1) << 4));
    int brow = ((grp >> 1) << 3) + (lane & 7);
    uint32_t bbase = base + (uint32_t)(brow * BSTRIDE + ((grp & 1) << 4));

    int r  = lane >> 2;
    int cp = (lane & 3) << 1;
    int d1r = (wrow << 4) + r;

    float c[64];
#pragma unroll
    for (int i = 0; i < 64; i++) c[i] = 0.f;

#pragma unroll
    for (int ks = 0; ks < 8; ks++) {
        uint32_t a[4];
        ldsm_x4(a, abase + ks * 32);
#pragma unroll
        for (int bt = 0; bt < 8; bt++) {
            uint32_t bb[4];
            ldsm_x4(bb, bbase + (uint32_t)(bt * 16 * BSTRIDE) + ks * 32);
            mma_bf16(c + bt * 8,     a, bb[0], bb[1]);
            mma_bf16(c + bt * 8 + 4, a, bb[2], bb[3]);
        }
    }

    float* outp = g_gpart
        + (((size_t)(which * BATCH + b) * MC + cblk) * DIM * DIM);
#pragma unroll
    for (int bt = 0; bt < 8; bt++) {
#pragma unroll
        for (int h = 0; h < 2; h++) {
            int nt = bt * 2 + h;
            const float* cc = c + bt * 8 + h * 4;
            float* p0 = outp + (size_t)d1r * DIM + nt * 8 + cp;
            *(float2*)p0 = make_float2(cc[0], cc[1]);
            *(float2*)(p0 + 8 * DIM) = make_float2(cc[2], cc[3]);
        }
    }
}

// ===========================================================================
// k_red: blockIdx.x<64 -> Frobenius partials; ==64 -> s1 per batch.
// ===========================================================================
__global__ __launch_bounds__(256) void k_red() {
    __shared__ float rr[8];
    __shared__ float sq[DIM], sk[DIM];
    int b = blockIdx.y;
    int tid = threadIdx.x;

    if (blockIdx.x < 64) {
        int e = blockIdx.x * 256 + tid;
        const float* pq = g_gpart + (size_t)(0 * BATCH + b) * MC * DIM * DIM + e;
        const float* pk = g_gpart + (size_t)(1 * BATCH + b) * MC * DIM * DIM + e;
        float gq = 0.f, gk = 0.f;
#pragma unroll
        for (int c = 0; c < MC; c++) {
            gq += pq[(size_t)c * DIM * DIM];
            gk += pk[(size_t)c * DIM * DIM];
        }
        float f = gq * gk;
#pragma unroll
        for (int o = 16; o; o >>= 1) f += __shfl_down_sync(0xffffffffu, f, o);
        if ((tid & 31) == 0) rr[tid >> 5] = f;
        __syncthreads();
        if (tid == 0) {
            float t = 0.f;
#pragma unroll
            for (int i = 0; i < 8; i++) t += rr[i];
            g_fpart[b * 64 + blockIdx.x] = t;
        }
    } else {
        int w = tid >> 7, d = tid & 127;
        const float* p = g_spart + ((w * BATCH + b) * MC) * DIM + d;
        float s = 0.f;
#pragma unroll
        for (int c = 0; c < MC; c++) s += p[c * DIM];
        if (w == 0) sq[d] = s; else sk[d] = s;
        __syncthreads();
        if (tid < 128) {
            float v = sq[d] * sk[d];
#pragma unroll
            for (int o = 16; o; o >>= 1) v += __shfl_down_sync(0xffffffffu, v, o);
            if ((tid & 31) == 0) rr[tid >> 5] = v;
        }
        __syncthreads();
        if (tid == 0) g_s1[b] = rr[0] + rr[1] + rr[2] + rr[3];
    }
}

// ===========================================================================
// k_loss: combine into scalar.
// loss = log(N) + [ (1/T)(s1 - sum dg) + (1/(2T^2))(F - sum dg^2) ] / (N*NB)
// ===========================================================================
__global__ __launch_bounds__(256) void k_loss(float* __restrict__ out) {
    __shared__ float red[256];
    int tid = threadIdx.x;
    const float halfT2 = 0.5f * INV_T * INV_T;
    float v = halfT2 * g_fpart[tid];
    if (tid < BATCH) v += INV_T * g_s1[tid];
    if (tid < NBLK)  v -= INV_T * g_dgpart[tid] + halfT2 * g_dg2part[tid];
    red[tid] = v;
    __syncthreads();
#pragma unroll
    for (int s = 128; s; s >>= 1) {
        if (tid < s) red[tid] += red[tid + s];
        __syncthreads();
    }
    if (tid == 0)
        out[0] = logf((float)NPTS) + red[0] / ((float)NPTS * (float)NB);
}

// ===========================================================================
extern "C" void kernel_launch(void* const* d_in, const int* in_sizes, int n_in,
                              void* d_out, int out_size) {
    const float* q = (const float*)d_in[0];
    const float* k = (const float*)d_in[1];
    float* out = (float*)d_out;
    (void)in_sizes; (void)n_in; (void)out_size;

    cudaFuncSetAttribute(k_main, cudaFuncAttributeMaxDynamicSharedMemorySize,
                         SB_TOTAL);

    k_main<<<dim3(MC, BATCH), 512, SB_TOTAL>>>(q, k);
    k_red<<<dim3(65, BATCH), 256>>>();
    k_loss<<<1, 256>>>(out);
}